// round 1
// baseline (speedup 1.0000x reference)
#include <cuda_runtime.h>

// Problem constants
#define BB   128   // batch
#define LL   196   // encoder length
#define EE   2048  // encoder dim
#define DD   1024  // decoder dim
#define AA   1024  // attention dim

// ---------------- device scratch (no allocations allowed) ----------------
__device__ float g_decq[BB * AA];     // Wd @ h + bd          [128,1024]
__device__ float g_u[BB * EE];        // Wq^T @ dec_q         [128,2048]
__device__ float g_c[BB];             // bq . dec_q           [128]
__device__ float g_m[BB * EE];        // softmax-weighted enc [128,2048]
__device__ float g_part[1 << 20];     // 4MB split-K partials (reused)

// =====================================================================
// Tiled fp32 GEMM with split-K: out_part[s][m][n] = sum_{k in chunk s} X[m,k]*W(k,n)
//   NN=true : W is [K,N] row-major  (W[k*N+n])
//   NN=false: W is [N,K] row-major  (W[n*K+k])
// M is always 128 (full batch). Tile: 128x64, k-step 16, 256 threads,
// 8x4 microtile per thread. Writes partials to g_part[blockIdx.y * 128*N ...].
// XSEL: 0 -> use X param, 1 -> g_decq, 2 -> g_m
// =====================================================================
template <bool NN, int XSEL>
__global__ void gemm128_kernel(const float* __restrict__ Xp,
                               const float* __restrict__ W,
                               int K, int N, int kchunk) {
    __shared__ float As[16 * 132];   // [k][m], padded stride 132
    __shared__ float Bs[16 * 68];    // [k][n], padded stride 68

    const float* X = (XSEL == 0) ? Xp : (XSEL == 1 ? (const float*)g_decq
                                                   : (const float*)g_m);

    const int t  = threadIdx.x;            // 256
    const int n0 = blockIdx.x * 64;
    const int k0 = blockIdx.y * kchunk;

    const int ty  = t >> 4;                // 0..15 -> 8 m-rows
    const int tx  = t & 15;                // 0..15 -> 4 n-cols
    const int m0t = ty * 8;
    const int n0t = tx * 4;

    float acc[8][4];
#pragma unroll
    for (int i = 0; i < 8; i++)
#pragma unroll
        for (int j = 0; j < 4; j++) acc[i][j] = 0.f;

    // A-load mapping: thread loads X[am][kt+akh .. kt+akh+7]
    const int am  = t >> 1;                // 0..127
    const int akh = (t & 1) * 8;           // 0 or 8
    // B-load mappings
    const int bkk = t >> 4;                // NN: 0..15
    const int bn4 = (t & 15) * 4;          // NN
    const int bnn = t >> 2;                // NT: 0..63
    const int bk4 = (t & 3) * 4;           // NT

    const int nkb = kchunk >> 4;
    for (int kb = 0; kb < nkb; kb++) {
        const int kt = k0 + kb * 16;

        // ---- stage A tile: As[kk][m] = X[m][kt+kk]
        {
            const float4* src = reinterpret_cast<const float4*>(X + am * K + kt + akh);
            float4 v0 = src[0];
            float4 v1 = src[1];
            float* col = As + am;
            col[(akh + 0) * 132] = v0.x;
            col[(akh + 1) * 132] = v0.y;
            col[(akh + 2) * 132] = v0.z;
            col[(akh + 3) * 132] = v0.w;
            col[(akh + 4) * 132] = v1.x;
            col[(akh + 5) * 132] = v1.y;
            col[(akh + 6) * 132] = v1.z;
            col[(akh + 7) * 132] = v1.w;
        }
        // ---- stage B tile: Bs[kk][n] = W(kt+kk, n0+n)
        if (NN) {
            float4 v = *reinterpret_cast<const float4*>(W + (size_t)(kt + bkk) * N + n0 + bn4);
            *reinterpret_cast<float4*>(&Bs[bkk * 68 + bn4]) = v;
        } else {
            float4 v = *reinterpret_cast<const float4*>(W + (size_t)(n0 + bnn) * K + kt + bk4);
            float* col = Bs + bnn;
            col[(bk4 + 0) * 68] = v.x;
            col[(bk4 + 1) * 68] = v.y;
            col[(bk4 + 2) * 68] = v.z;
            col[(bk4 + 3) * 68] = v.w;
        }
        __syncthreads();

#pragma unroll
        for (int kk = 0; kk < 16; kk++) {
            const float* ar = &As[kk * 132 + m0t];
            float4 a0 = *reinterpret_cast<const float4*>(ar);
            float4 a1 = *reinterpret_cast<const float4*>(ar + 4);
            float4 bv = *reinterpret_cast<const float4*>(&Bs[kk * 68 + n0t]);
            float av[8] = {a0.x, a0.y, a0.z, a0.w, a1.x, a1.y, a1.z, a1.w};
            float bw[4] = {bv.x, bv.y, bv.z, bv.w};
#pragma unroll
            for (int i = 0; i < 8; i++)
#pragma unroll
                for (int j = 0; j < 4; j++) acc[i][j] += av[i] * bw[j];
        }
        __syncthreads();
    }

    float* pb = g_part + (size_t)blockIdx.y * (BB * N);
#pragma unroll
    for (int i = 0; i < 8; i++) {
        float4 v = {acc[i][0], acc[i][1], acc[i][2], acc[i][3]};
        *reinterpret_cast<float4*>(pb + (size_t)(m0t + i) * N + n0 + n0t) = v;
    }
}

// =====================================================================
// Split-K reduce + optional bias. OUTSEL: 0 -> out param, 1 -> g_decq, 2 -> g_u
// =====================================================================
template <int OUTSEL>
__global__ void reduce_add_kernel(float* __restrict__ outp,
                                  const float* __restrict__ bias,
                                  int S, int MN, int N) {
    float* out = (OUTSEL == 0) ? outp : (OUTSEL == 1 ? (float*)g_decq : (float*)g_u);
    int i = (blockIdx.x * blockDim.x + threadIdx.x) * 4;
    if (i >= MN) return;
    float4 s = *reinterpret_cast<const float4*>(g_part + i);
    for (int k = 1; k < S; k++) {
        float4 v = *reinterpret_cast<const float4*>(g_part + (size_t)k * MN + i);
        s.x += v.x; s.y += v.y; s.z += v.z; s.w += v.w;
    }
    if (bias) {
        float4 bv = *reinterpret_cast<const float4*>(bias + (i % N));
        s.x += bv.x; s.y += bv.y; s.z += bv.z; s.w += bv.w;
    }
    *reinterpret_cast<float4*>(out + i) = s;
}

// =====================================================================
// c[b] = bq . dec_q[b]   (fixed-order: warp shuffle + sequential warp sums)
// =====================================================================
__global__ void cvec_kernel(const float* __restrict__ bq) {
    const int b = blockIdx.x;
    const int t = threadIdx.x;  // 256
    const float* dq = g_decq + b * AA;
    float s = 0.f;
    for (int a = t; a < AA; a += 256) s += bq[a] * dq[a];
#pragma unroll
    for (int o = 16; o > 0; o >>= 1) s += __shfl_xor_sync(0xffffffffu, s, o);
    __shared__ float red[8];
    if ((t & 31) == 0) red[t >> 5] = s;
    __syncthreads();
    if (t == 0) {
        float tot = 0.f;
        for (int i = 0; i < 8; i++) tot += red[i];
        g_c[b] = tot;
    }
}

// =====================================================================
// Fused single-pass attention over encoder_outputs:
//   energy_l = tanh(enc[b,l,:].u[b] + c[b]); w_l = exp(energy_l)
//   m[b,:]   = (sum_l w_l * enc[b,l,:]) / (sum_l w_l)
// One CTA per batch b. 512 threads. Chunks of 16 rows: phase (a) 16 warps
// compute dots (DRAM stream), phase (b) weighted-sum re-reads the chunk
// (L1-resident, 128KB).
// =====================================================================
__global__ void fused_attn_kernel(const float* __restrict__ enc) {
    const int b    = blockIdx.x;
    const int t    = threadIdx.x;   // 512
    const int warp = t >> 5;
    const int lane = t & 31;

    __shared__ float u_s[EE];
    __shared__ float wexp_s[16];
    __shared__ float wden_s[16];
    __shared__ float s_inv;

    // stage u[b] into smem
    reinterpret_cast<float4*>(u_s)[t] =
        reinterpret_cast<const float4*>(g_u + (size_t)b * EE)[t];
    const float c_b = g_c[b];
    __syncthreads();

    const float* encb = enc + (size_t)b * LL * EE;
    float4 macc = {0.f, 0.f, 0.f, 0.f};
    float wden = 0.f;

    for (int c0 = 0; c0 < LL; c0 += 16) {
        const int l = c0 + warp;
        float w = 0.f;
        if (l < LL) {
            const float4* row4 = reinterpret_cast<const float4*>(encb + (size_t)l * EE);
            const float4* us4  = reinterpret_cast<const float4*>(u_s);
            float dot = 0.f;
#pragma unroll
            for (int i = 0; i < 16; i++) {
                const int f = lane + 32 * i;
                float4 v  = row4[f];
                float4 uu = us4[f];
                dot += v.x * uu.x + v.y * uu.y + v.z * uu.z + v.w * uu.w;
            }
#pragma unroll
            for (int o = 16; o > 0; o >>= 1)
                dot += __shfl_xor_sync(0xffffffffu, dot, o);
            w = __expf(tanhf(dot + c_b));
        }
        if (lane == 0) { wexp_s[warp] = w; wden += w; }
        __syncthreads();

        const int nr = (LL - c0) < 16 ? (LL - c0) : 16;
        const float4* base = reinterpret_cast<const float4*>(encb + (size_t)c0 * EE) + t;
        for (int r = 0; r < nr; r++) {
            const float wv = wexp_s[r];
            float4 v = base[(size_t)r * (EE / 4)];
            macc.x += wv * v.x; macc.y += wv * v.y;
            macc.z += wv * v.z; macc.w += wv * v.w;
        }
        __syncthreads();
    }

    if (lane == 0) wden_s[warp] = wden;
    __syncthreads();
    if (t == 0) {
        float s = 0.f;
        for (int i = 0; i < 16; i++) s += wden_s[i];
        s_inv = 1.f / s;
    }
    __syncthreads();
    const float inv = s_inv;
    float4 o = {macc.x * inv, macc.y * inv, macc.z * inv, macc.w * inv};
    reinterpret_cast<float4*>(g_m + (size_t)b * EE)[t] = o;
}

// =====================================================================
// Launcher
// =====================================================================
extern "C" void kernel_launch(void* const* d_in, const int* in_sizes, int n_in,
                              void* d_out, int out_size) {
    const float* enc = (const float*)d_in[0];  // [128,196,2048]
    const float* dh  = (const float*)d_in[1];  // [128,1024]
    const float* Wq  = (const float*)d_in[2];  // [1024,2048]  (A,E)
    const float* bq  = (const float*)d_in[3];  // [1024]
    const float* Wv  = (const float*)d_in[4];  // [1024,2048]  (A,E)
    const float* bv  = (const float*)d_in[5];  // [1024]
    const float* Wd  = (const float*)d_in[6];  // [1024,1024]  (A,D)
    const float* bd  = (const float*)d_in[7];  // [1024]
    float* out = (float*)d_out;                // [128,1024]

    // 1) dec_q = h @ Wd^T + bd      (NT: W=[A,D], reduce over D=1024, split 8)
    gemm128_kernel<false, 0><<<dim3(AA / 64, 8), 256>>>(dh, Wd, DD, AA, DD / 8);
    reduce_add_kernel<1><<<(BB * AA) / (256 * 4), 256>>>(nullptr, bd, 8, BB * AA, AA);

    // 2) c = dec_q . bq
    cvec_kernel<<<BB, 256>>>(bq);

    // 3) u = dec_q @ Wq             (NN: W=[A,E], reduce over A=1024, split 4)
    gemm128_kernel<true, 1><<<dim3(EE / 64, 4), 256>>>(nullptr, Wq, AA, EE, AA / 4);
    reduce_add_kernel<2><<<(BB * EE) / (256 * 4), 256>>>(nullptr, nullptr, 4, BB * EE, EE);

    // 4) fused: energies + softmax + weighted encoder sum -> m
    fused_attn_kernel<<<BB, 512>>>(enc);

    // 5) context = m @ Wv^T + bv    (NT: W=[A,E], reduce over E=2048, split 8)
    gemm128_kernel<false, 2><<<dim3(AA / 64, 8), 256>>>(nullptr, Wv, EE, AA, EE / 8);
    reduce_add_kernel<0><<<(BB * AA) / (256 * 4), 256>>>(out, bv, 8, BB * AA, AA);
}

// round 2
// speedup vs baseline: 1.1468x; 1.1468x over previous
#include <cuda_runtime.h>
#include <cstdint>

// Problem constants
#define BB   128   // batch
#define LL   196   // encoder length
#define EE   2048  // encoder dim
#define DD   1024  // decoder dim
#define AA   1024  // attention dim

// ---------------- device scratch (no allocations allowed) ----------------
__device__ float g_decq[BB * AA];        // Wd @ h + bd           [128,1024]
__device__ float g_u[BB * EE];           // Wq^T @ dec_q          [128,2048]
__device__ float g_c[BB];                // bq . dec_q            [128]
__device__ float g_m[BB * EE];           // softmax-weighted enc  [128,2048]
__device__ float g_part[1 << 21];        // 8MB split-K partials
__device__ float g_fpart[2 * BB * EE];   // fused partial sums
__device__ float g_fden[2 * BB];         // fused partial denominators

// ---------------- tf32 helpers ----------------
__device__ __forceinline__ void split_tf32(float x, uint32_t& hi, uint32_t& lo) {
    asm("cvt.rna.tf32.f32 %0, %1;" : "=r"(hi) : "f"(x));
    float l = x - __uint_as_float(hi);
    asm("cvt.rna.tf32.f32 %0, %1;" : "=r"(lo) : "f"(l));
}

__device__ __forceinline__ void mma_tf32(float* c, const uint32_t* a, const uint32_t* b) {
    asm volatile(
        "mma.sync.aligned.m16n8k8.row.col.f32.tf32.tf32.f32 "
        "{%0,%1,%2,%3}, {%4,%5,%6,%7}, {%8,%9}, {%0,%1,%2,%3};"
        : "+f"(c[0]), "+f"(c[1]), "+f"(c[2]), "+f"(c[3])
        : "r"(a[0]), "r"(a[1]), "r"(a[2]), "r"(a[3]), "r"(b[0]), "r"(b[1]));
}

// =====================================================================
// Tensor-core tf32 GEMM w/ split-K partials:
//   part[s][m][n] = sum_{k in chunk s} X[m,k] * W(k,n)
//   NN=true : W is [K,N] row-major;  NN=false: W is [N,K] row-major
// Block tile: M=128 x N=64, K-step 32. 256 threads = 8 warps (4M x 2N),
// warp tile 32x32 -> 2x4 m16n8k8 positions, 3 mma per position (hi/lo).
// XSEL: 0 -> X param, 1 -> g_decq, 2 -> g_m
// =====================================================================
template <bool NN, int XSEL>
__global__ void __launch_bounds__(256, 2)
gemm_tc(const float* __restrict__ Xp, const float* __restrict__ W,
        int K, int N, int kchunk) {
    __shared__ float As[128][36];   // [m][k], pad 36 -> conflict-free frag reads
    __shared__ float Bs[32][68];    // [k][n], pad 68 -> conflict-free frag reads

    const float* X = (XSEL == 0) ? Xp : (XSEL == 1 ? (const float*)g_decq
                                                   : (const float*)g_m);
    const int t     = threadIdx.x;
    const int warp  = t >> 5;
    const int lane  = t & 31;
    const int group = lane >> 2;    // 0..7
    const int tg    = lane & 3;     // 0..3
    const int wm    = warp & 3;     // 0..3  (M)
    const int wn    = warp >> 2;    // 0..1  (N)
    const int n0    = blockIdx.x * 64;
    const int k0    = blockIdx.y * kchunk;

    float c[2][4][4];
#pragma unroll
    for (int mi = 0; mi < 2; mi++)
#pragma unroll
        for (int ni = 0; ni < 4; ni++)
#pragma unroll
            for (int r = 0; r < 4; r++) c[mi][ni][r] = 0.f;

    const int nkb = kchunk >> 5;
    for (int kb = 0; kb < nkb; kb++) {
        const int kt = k0 + kb * 32;

        // stage A tile: 128 x 32 fp32 (1024 float4, 4 per thread)
#pragma unroll
        for (int j = 0; j < 4; j++) {
            int idx = t + 256 * j;
            int row = idx >> 3;
            int kq  = idx & 7;
            float4 v = *reinterpret_cast<const float4*>(X + (size_t)row * K + kt + kq * 4);
            *reinterpret_cast<float4*>(&As[row][kq * 4]) = v;
        }
        // stage B tile: 32 x 64
        if (NN) {
#pragma unroll
            for (int j = 0; j < 2; j++) {
                int idx = t + 256 * j;
                int r   = idx >> 4;
                int nq  = idx & 15;
                float4 v = *reinterpret_cast<const float4*>(W + (size_t)(kt + r) * N + n0 + nq * 4);
                *reinterpret_cast<float4*>(&Bs[r][nq * 4]) = v;
            }
        } else {
#pragma unroll
            for (int j = 0; j < 2; j++) {
                int idx = t + 256 * j;
                int n   = idx >> 3;
                int kq  = idx & 7;
                float4 v = *reinterpret_cast<const float4*>(W + (size_t)(n0 + n) * K + kt + kq * 4);
                Bs[kq * 4 + 0][n] = v.x;
                Bs[kq * 4 + 1][n] = v.y;
                Bs[kq * 4 + 2][n] = v.z;
                Bs[kq * 4 + 3][n] = v.w;
            }
        }
        __syncthreads();

#pragma unroll
        for (int ks = 0; ks < 4; ks++) {
            const int koff = ks * 8;
            uint32_t ahi[2][4], alo[2][4];
#pragma unroll
            for (int mi = 0; mi < 2; mi++) {
                const int rm = wm * 32 + mi * 16 + group;
                float a0 = As[rm][koff + tg];
                float a1 = As[rm + 8][koff + tg];
                float a2 = As[rm][koff + tg + 4];
                float a3 = As[rm + 8][koff + tg + 4];
                split_tf32(a0, ahi[mi][0], alo[mi][0]);
                split_tf32(a1, ahi[mi][1], alo[mi][1]);
                split_tf32(a2, ahi[mi][2], alo[mi][2]);
                split_tf32(a3, ahi[mi][3], alo[mi][3]);
            }
#pragma unroll
            for (int ni = 0; ni < 4; ni++) {
                const int nb = wn * 32 + ni * 8 + group;
                float b0 = Bs[koff + tg][nb];
                float b1 = Bs[koff + tg + 4][nb];
                uint32_t bhi[2], blo[2];
                split_tf32(b0, bhi[0], blo[0]);
                split_tf32(b1, bhi[1], blo[1]);
#pragma unroll
                for (int mi = 0; mi < 2; mi++) {
                    mma_tf32(c[mi][ni], ahi[mi], bhi);
                    mma_tf32(c[mi][ni], ahi[mi], blo);
                    mma_tf32(c[mi][ni], alo[mi], bhi);
                }
            }
        }
        __syncthreads();
    }

    // write partials
    float* pb = g_part + (size_t)blockIdx.y * (BB * N);
#pragma unroll
    for (int mi = 0; mi < 2; mi++) {
        const int row0 = wm * 32 + mi * 16 + group;
#pragma unroll
        for (int ni = 0; ni < 4; ni++) {
            const int col = n0 + wn * 32 + ni * 8 + 2 * tg;
            float2 v01 = {c[mi][ni][0], c[mi][ni][1]};
            float2 v23 = {c[mi][ni][2], c[mi][ni][3]};
            *reinterpret_cast<float2*>(pb + (size_t)row0 * N + col) = v01;
            *reinterpret_cast<float2*>(pb + (size_t)(row0 + 8) * N + col) = v23;
        }
    }
}

// =====================================================================
// Split-K reduce + optional bias. OUTSEL: 0 -> out param, 1 -> g_decq, 2 -> g_u
// =====================================================================
template <int OUTSEL>
__global__ void reduce_add_kernel(float* __restrict__ outp,
                                  const float* __restrict__ bias,
                                  int S, int MN, int N) {
    float* out = (OUTSEL == 0) ? outp : (OUTSEL == 1 ? (float*)g_decq : (float*)g_u);
    int i = (blockIdx.x * blockDim.x + threadIdx.x) * 4;
    if (i >= MN) return;
    float4 s = *reinterpret_cast<const float4*>(g_part + i);
    for (int k = 1; k < S; k++) {
        float4 v = *reinterpret_cast<const float4*>(g_part + (size_t)k * MN + i);
        s.x += v.x; s.y += v.y; s.z += v.z; s.w += v.w;
    }
    if (bias) {
        float4 bv = *reinterpret_cast<const float4*>(bias + (i % N));
        s.x += bv.x; s.y += bv.y; s.z += bv.z; s.w += bv.w;
    }
    *reinterpret_cast<float4*>(out + i) = s;
}

// =====================================================================
// c[b] = bq . dec_q[b]
// =====================================================================
__global__ void cvec_kernel(const float* __restrict__ bq) {
    const int b = blockIdx.x;
    const int t = threadIdx.x;  // 256
    const float* dq = g_decq + b * AA;
    float s = 0.f;
    for (int a = t; a < AA; a += 256) s += bq[a] * dq[a];
#pragma unroll
    for (int o = 16; o > 0; o >>= 1) s += __shfl_xor_sync(0xffffffffu, s, o);
    __shared__ float red[8];
    if ((t & 31) == 0) red[t >> 5] = s;
    __syncthreads();
    if (t == 0) {
        float tot = 0.f;
        for (int i = 0; i < 8; i++) tot += red[i];
        g_c[b] = tot;
    }
}

// =====================================================================
// Fused attention pass, split 2-ways over L. grid (BB, 2), 512 threads.
// 8-row chunks: phase (a) pair-warp dot products (stream from DRAM),
// phase (b) weighted sum re-reads the 64KB chunk from L1.
// Writes UNNORMALIZED partial sums + partial denominators.
// =====================================================================
__global__ void fused_attn_kernel(const float* __restrict__ enc) {
    const int b    = blockIdx.x;
    const int s    = blockIdx.y;       // 0..1
    const int t    = threadIdx.x;      // 512
    const int warp = t >> 5;
    const int lane = t & 31;
    const int lstart = s * 98;
    const int lend   = (lstart + 98 < LL) ? lstart + 98 : LL;

    __shared__ float u_s[EE];
    __shared__ float pdot[8][2];
    __shared__ float wexp_s[8];
    __shared__ float wden_sh;

    reinterpret_cast<float4*>(u_s)[t] =
        reinterpret_cast<const float4*>(g_u + (size_t)b * EE)[t];
    if (t == 0) wden_sh = 0.f;
    const float c_b = g_c[b];
    __syncthreads();

    const float* encb = enc + (size_t)b * LL * EE;
    float4 macc = {0.f, 0.f, 0.f, 0.f};

    for (int c0 = lstart; c0 < lend; c0 += 8) {
        const int nr = (lend - c0) < 8 ? (lend - c0) : 8;
        const int lw   = warp >> 1;    // row within chunk
        const int half = warp & 1;     // which half of the 2048-dim dot

        if (lw < nr) {
            const float4* row4 =
                reinterpret_cast<const float4*>(encb + (size_t)(c0 + lw) * EE) + half * 256;
            const float4* us4 = reinterpret_cast<const float4*>(u_s) + half * 256;
            float d = 0.f;
#pragma unroll
            for (int i = 0; i < 8; i++) {
                const int f = lane + 32 * i;
                float4 v  = row4[f];
                float4 uu = us4[f];
                d += v.x * uu.x + v.y * uu.y + v.z * uu.z + v.w * uu.w;
            }
#pragma unroll
            for (int o = 16; o > 0; o >>= 1)
                d += __shfl_xor_sync(0xffffffffu, d, o);
            if (lane == 0) pdot[lw][half] = d;
        }
        __syncthreads();

        if (t < nr)
            wexp_s[t] = __expf(tanhf(pdot[t][0] + pdot[t][1] + c_b));
        __syncthreads();

        if (t == 0) {
            float acc = 0.f;
            for (int r = 0; r < nr; r++) acc += wexp_s[r];
            wden_sh += acc;
        }
        const float4* base = reinterpret_cast<const float4*>(encb + (size_t)c0 * EE) + t;
        for (int r = 0; r < nr; r++) {
            const float wv = wexp_s[r];
            float4 v = base[(size_t)r * (EE / 4)];
            macc.x += wv * v.x; macc.y += wv * v.y;
            macc.z += wv * v.z; macc.w += wv * v.w;
        }
        __syncthreads();
    }

    float* pp = g_fpart + ((size_t)s * BB + b) * EE;
    reinterpret_cast<float4*>(pp)[t] = macc;
    if (t == 0) g_fden[s * BB + b] = wden_sh;
}

// =====================================================================
// Combine the 2 L-splits: m[b] = (p0 + p1) / (d0 + d1)
// =====================================================================
__global__ void combine_kernel() {
    const int b = blockIdx.x;
    const int t = threadIdx.x;  // 512
    const float inv = 1.f / (g_fden[b] + g_fden[BB + b]);
    float4 p0 = reinterpret_cast<const float4*>(g_fpart + (size_t)b * EE)[t];
    float4 p1 = reinterpret_cast<const float4*>(g_fpart + ((size_t)BB + b) * EE)[t];
    float4 o = {(p0.x + p1.x) * inv, (p0.y + p1.y) * inv,
                (p0.z + p1.z) * inv, (p0.w + p1.w) * inv};
    reinterpret_cast<float4*>(g_m + (size_t)b * EE)[t] = o;
}

// =====================================================================
// Launcher
// =====================================================================
extern "C" void kernel_launch(void* const* d_in, const int* in_sizes, int n_in,
                              void* d_out, int out_size) {
    const float* enc = (const float*)d_in[0];  // [128,196,2048]
    const float* dh  = (const float*)d_in[1];  // [128,1024]
    const float* Wq  = (const float*)d_in[2];  // [1024,2048]  (A,E)
    const float* bq  = (const float*)d_in[3];  // [1024]
    const float* Wv  = (const float*)d_in[4];  // [1024,2048]  (A,E)
    const float* bv  = (const float*)d_in[5];  // [1024]
    const float* Wd  = (const float*)d_in[6];  // [1024,1024]  (A,D)
    const float* bd  = (const float*)d_in[7];  // [1024]
    float* out = (float*)d_out;                // [128,1024]

    // 1) dec_q = h @ Wd^T + bd   (NT, K=D=1024, N=A=1024, split 8)
    gemm_tc<false, 0><<<dim3(AA / 64, 8), 256>>>(dh, Wd, DD, AA, DD / 8);
    reduce_add_kernel<1><<<(BB * AA) / (256 * 4), 256>>>(nullptr, bd, 8, BB * AA, AA);

    // 2) c = dec_q . bq
    cvec_kernel<<<BB, 256>>>(bq);

    // 3) u = dec_q @ Wq          (NN, K=A=1024, N=E=2048, split 8)
    gemm_tc<true, 1><<<dim3(EE / 64, 8), 256>>>(nullptr, Wq, AA, EE, AA / 8);
    reduce_add_kernel<2><<<(BB * EE) / (256 * 4), 256>>>(nullptr, nullptr, 8, BB * EE, EE);

    // 4) fused: energies + softmax weights + weighted encoder sum (split 2)
    fused_attn_kernel<<<dim3(BB, 2), 512>>>(enc);
    combine_kernel<<<BB, 512>>>();

    // 5) context = m @ Wv^T + bv (NT, K=E=2048, N=A=1024, split 16)
    gemm_tc<false, 2><<<dim3(AA / 64, 16), 256>>>(nullptr, Wv, EE, AA, EE / 16);
    reduce_add_kernel<0><<<(BB * AA) / (256 * 4), 256>>>(out, bv, 16, BB * AA, AA);
}

// round 3
// speedup vs baseline: 1.1757x; 1.0252x over previous
#include <cuda_runtime.h>
#include <cstdint>

// Problem constants
#define BB   128   // batch
#define LL   196   // encoder length
#define EE   2048  // encoder dim
#define DD   1024  // decoder dim
#define AA   1024  // attention dim

// ---------------- device scratch (no allocations allowed) ----------------
__device__ float g_decq[BB * AA];        // Wd @ h + bd           [128,1024]
__device__ float g_u[BB * EE];           // Wq^T @ dec_q          [128,2048]
__device__ float g_c[BB];                // bq . dec_q            [128]
__device__ float g_part[1 << 21];        // 8MB split-K partials
__device__ float g_fpart[2 * BB * EE];   // fused partial sums (unnormalized)
__device__ float g_fden[2 * BB];         // fused partial denominators

// ---------------- tf32 helpers ----------------
__device__ __forceinline__ uint32_t tf32_hi(float x) {
    uint32_t h;
    asm("cvt.rna.tf32.f32 %0, %1;" : "=r"(h) : "f"(x));
    return h;
}
__device__ __forceinline__ void split2(float x, uint32_t& hi, uint32_t& lo) {
    hi = tf32_hi(x);
    lo = tf32_hi(x - __uint_as_float(hi));
}

__device__ __forceinline__ void mma_tf32(float* c, const uint32_t* a, const uint32_t* b) {
    asm volatile(
        "mma.sync.aligned.m16n8k8.row.col.f32.tf32.tf32.f32 "
        "{%0,%1,%2,%3}, {%4,%5,%6,%7}, {%8,%9}, {%0,%1,%2,%3};"
        : "+f"(c[0]), "+f"(c[1]), "+f"(c[2]), "+f"(c[3])
        : "r"(a[0]), "r"(a[1]), "r"(a[2]), "r"(a[3]), "r"(b[0]), "r"(b[1]));
}

// Pre-split hi/lo smem planes, double buffered.
struct SmemGemm {
    uint32_t Ahi[2][128][36];
    uint32_t Alo[2][128][36];
    uint32_t Bhi[2][32][68];
    uint32_t Blo[2][32][68];
};

// =====================================================================
// Tensor-core tf32x3 GEMM, split-K partials:
//   part[s][m][n] = sum_{k in chunk s} X[m,k] * W(k,n)
//   NN=true : W is [K,N] row-major;  NN=false: W is [N,K] row-major
// 256 threads = 8 warps (4M x 2N), block tile 128x64, K-step 32.
// hi/lo tf32 split happens ONCE at staging; inner loop is pure LDS+MMA.
// XSEL: 0 -> X param, 1 -> g_decq, 2 -> g_fpart[0]+g_fpart[1]
// =====================================================================
template <bool NN, int XSEL>
__global__ void __launch_bounds__(256)
gemm_tc(const float* __restrict__ Xp, const float* __restrict__ W,
        int K, int N, int kchunk) {
    extern __shared__ SmemGemm sm_g[];
    SmemGemm* s = sm_g;

    const float* X = (XSEL == 1) ? (const float*)g_decq : Xp;

    const int t     = threadIdx.x;
    const int warp  = t >> 5;
    const int lane  = t & 31;
    const int group = lane >> 2;    // 0..7
    const int tg    = lane & 3;     // 0..3
    const int wm    = warp & 3;     // 0..3  (M)
    const int wn    = warp >> 2;    // 0..1  (N)
    const int n0    = blockIdx.x * 64;
    const int k0    = blockIdx.y * kchunk;

    float c[2][4][4];
#pragma unroll
    for (int mi = 0; mi < 2; mi++)
#pragma unroll
        for (int ni = 0; ni < 4; ni++)
#pragma unroll
            for (int r = 0; r < 4; r++) c[mi][ni][r] = 0.f;

    float4 ra[4];
    float4 rb[2];

    // ---- load tile (gmem -> regs)
    auto loadA = [&](int kt) {
#pragma unroll
        for (int j = 0; j < 4; j++) {
            const int idx = t + 256 * j;
            const int row = idx >> 3;
            const int kq  = idx & 7;
            if (XSEL == 2) {
                float4 p0 = *reinterpret_cast<const float4*>(
                    g_fpart + (size_t)row * EE + kt + kq * 4);
                float4 p1 = *reinterpret_cast<const float4*>(
                    g_fpart + (size_t)(BB + row) * EE + kt + kq * 4);
                ra[j] = make_float4(p0.x + p1.x, p0.y + p1.y, p0.z + p1.z, p0.w + p1.w);
            } else {
                ra[j] = *reinterpret_cast<const float4*>(X + (size_t)row * K + kt + kq * 4);
            }
        }
    };
    auto loadB = [&](int kt) {
        if (NN) {
#pragma unroll
            for (int j = 0; j < 2; j++) {
                const int idx = t + 256 * j;
                const int r   = idx >> 4;
                const int nq  = idx & 15;
                rb[j] = *reinterpret_cast<const float4*>(W + (size_t)(kt + r) * N + n0 + nq * 4);
            }
        } else {
#pragma unroll
            for (int j = 0; j < 2; j++) {
                const int idx = t + 256 * j;
                const int n   = idx >> 3;
                const int kq  = idx & 7;
                rb[j] = *reinterpret_cast<const float4*>(W + (size_t)(n0 + n) * K + kt + kq * 4);
            }
        }
    };
    // ---- split + store (regs -> smem planes)
    auto storeAB = [&](int bb) {
#pragma unroll
        for (int j = 0; j < 4; j++) {
            const int idx = t + 256 * j;
            const int row = idx >> 3;
            const int kq  = idx & 7;
            uint4 h, l;
            split2(ra[j].x, h.x, l.x);
            split2(ra[j].y, h.y, l.y);
            split2(ra[j].z, h.z, l.z);
            split2(ra[j].w, h.w, l.w);
            *reinterpret_cast<uint4*>(&s->Ahi[bb][row][kq * 4]) = h;
            *reinterpret_cast<uint4*>(&s->Alo[bb][row][kq * 4]) = l;
        }
        if (NN) {
#pragma unroll
            for (int j = 0; j < 2; j++) {
                const int idx = t + 256 * j;
                const int r   = idx >> 4;
                const int nq  = idx & 15;
                uint4 h, l;
                split2(rb[j].x, h.x, l.x);
                split2(rb[j].y, h.y, l.y);
                split2(rb[j].z, h.z, l.z);
                split2(rb[j].w, h.w, l.w);
                *reinterpret_cast<uint4*>(&s->Bhi[bb][r][nq * 4]) = h;
                *reinterpret_cast<uint4*>(&s->Blo[bb][r][nq * 4]) = l;
            }
        } else {
#pragma unroll
            for (int j = 0; j < 2; j++) {
                const int idx = t + 256 * j;
                const int n   = idx >> 3;
                const int kq  = idx & 7;
                uint32_t h, l;
                split2(rb[j].x, h, l); s->Bhi[bb][kq * 4 + 0][n] = h; s->Blo[bb][kq * 4 + 0][n] = l;
                split2(rb[j].y, h, l); s->Bhi[bb][kq * 4 + 1][n] = h; s->Blo[bb][kq * 4 + 1][n] = l;
                split2(rb[j].z, h, l); s->Bhi[bb][kq * 4 + 2][n] = h; s->Blo[bb][kq * 4 + 2][n] = l;
                split2(rb[j].w, h, l); s->Bhi[bb][kq * 4 + 3][n] = h; s->Blo[bb][kq * 4 + 3][n] = l;
            }
        }
    };
    // ---- compute one K-32 tile from buffer bb (pure LDS + MMA)
    auto compute = [&](int bb) {
#pragma unroll
        for (int ks = 0; ks < 4; ks++) {
            const int koff = ks * 8;
            uint32_t ah[2][4], al[2][4];
#pragma unroll
            for (int mi = 0; mi < 2; mi++) {
                const int rm = wm * 32 + mi * 16 + group;
                ah[mi][0] = s->Ahi[bb][rm][koff + tg];
                ah[mi][1] = s->Ahi[bb][rm + 8][koff + tg];
                ah[mi][2] = s->Ahi[bb][rm][koff + tg + 4];
                ah[mi][3] = s->Ahi[bb][rm + 8][koff + tg + 4];
                al[mi][0] = s->Alo[bb][rm][koff + tg];
                al[mi][1] = s->Alo[bb][rm + 8][koff + tg];
                al[mi][2] = s->Alo[bb][rm][koff + tg + 4];
                al[mi][3] = s->Alo[bb][rm + 8][koff + tg + 4];
            }
#pragma unroll
            for (int ni = 0; ni < 4; ni++) {
                const int nb = wn * 32 + ni * 8 + group;
                uint32_t bh[2], bl[2];
                bh[0] = s->Bhi[bb][koff + tg][nb];
                bh[1] = s->Bhi[bb][koff + tg + 4][nb];
                bl[0] = s->Blo[bb][koff + tg][nb];
                bl[1] = s->Blo[bb][koff + tg + 4][nb];
#pragma unroll
                for (int mi = 0; mi < 2; mi++) {
                    mma_tf32(c[mi][ni], ah[mi], bh);
                    mma_tf32(c[mi][ni], ah[mi], bl);
                    mma_tf32(c[mi][ni], al[mi], bh);
                }
            }
        }
    };

    // ---- pipelined main loop
    loadA(k0);
    loadB(k0);
    storeAB(0);
    __syncthreads();

    const int nkb = kchunk >> 5;
    for (int kb = 0; kb < nkb; kb++) {
        const int cur = kb & 1;
        if (kb + 1 < nkb) {
            loadA(k0 + (kb + 1) * 32);
            loadB(k0 + (kb + 1) * 32);
        }
        compute(cur);
        if (kb + 1 < nkb) storeAB(cur ^ 1);
        __syncthreads();
    }

    // ---- write partials
    float* pb = g_part + (size_t)blockIdx.y * (BB * N);
#pragma unroll
    for (int mi = 0; mi < 2; mi++) {
        const int row0 = wm * 32 + mi * 16 + group;
#pragma unroll
        for (int ni = 0; ni < 4; ni++) {
            const int col = n0 + wn * 32 + ni * 8 + 2 * tg;
            float2 v01 = {c[mi][ni][0], c[mi][ni][1]};
            float2 v23 = {c[mi][ni][2], c[mi][ni][3]};
            *reinterpret_cast<float2*>(pb + (size_t)row0 * N + col) = v01;
            *reinterpret_cast<float2*>(pb + (size_t)(row0 + 8) * N + col) = v23;
        }
    }
}

// =====================================================================
// Split-K reduce (+bias, +optional per-row 1/sum(w) scale for context)
// OUTSEL: 0 -> out param, 1 -> g_decq, 2 -> g_u
// =====================================================================
template <int OUTSEL, bool SCALE>
__global__ void reduce_add_kernel(float* __restrict__ outp,
                                  const float* __restrict__ bias,
                                  int S, int MN, int N) {
    float* out = (OUTSEL == 0) ? outp : (OUTSEL == 1 ? (float*)g_decq : (float*)g_u);
    int i = (blockIdx.x * blockDim.x + threadIdx.x) * 4;
    if (i >= MN) return;
    float4 s = *reinterpret_cast<const float4*>(g_part + i);
    for (int k = 1; k < S; k++) {
        float4 v = *reinterpret_cast<const float4*>(g_part + (size_t)k * MN + i);
        s.x += v.x; s.y += v.y; s.z += v.z; s.w += v.w;
    }
    if (SCALE) {
        const int m = i / N;
        const float inv = 1.f / (g_fden[m] + g_fden[BB + m]);
        s.x *= inv; s.y *= inv; s.z *= inv; s.w *= inv;
    }
    if (bias) {
        float4 bv = *reinterpret_cast<const float4*>(bias + (i % N));
        s.x += bv.x; s.y += bv.y; s.z += bv.z; s.w += bv.w;
    }
    *reinterpret_cast<float4*>(out + i) = s;
}

// =====================================================================
// c[b] = bq . dec_q[b]
// =====================================================================
__global__ void cvec_kernel(const float* __restrict__ bq) {
    const int b = blockIdx.x;
    const int t = threadIdx.x;  // 256
    const float* dq = g_decq + b * AA;
    float s = 0.f;
    for (int a = t; a < AA; a += 256) s += bq[a] * dq[a];
#pragma unroll
    for (int o = 16; o > 0; o >>= 1) s += __shfl_xor_sync(0xffffffffu, s, o);
    __shared__ float red[8];
    if ((t & 31) == 0) red[t >> 5] = s;
    __syncthreads();
    if (t == 0) {
        float tot = 0.f;
        for (int i = 0; i < 8; i++) tot += red[i];
        g_c[b] = tot;
    }
}

// =====================================================================
// Fused attention pass, split 2-ways over L. grid (BB, 2), 512 threads.
// 8-row chunks: phase (a) pair-warp dot products (DRAM stream),
// phase (b) weighted sum re-reads the 64KB chunk from L1.
// Writes UNNORMALIZED partial sums + partial denominators.
// =====================================================================
__global__ void fused_attn_kernel(const float* __restrict__ enc) {
    const int b    = blockIdx.x;
    const int sp   = blockIdx.y;       // 0..1
    const int t    = threadIdx.x;      // 512
    const int warp = t >> 5;
    const int lane = t & 31;
    const int lstart = sp * 98;
    const int lend   = (lstart + 98 < LL) ? lstart + 98 : LL;

    __shared__ float u_s[EE];
    __shared__ float pdot[8][2];
    __shared__ float wexp_s[8];
    __shared__ float wden_sh;

    reinterpret_cast<float4*>(u_s)[t] =
        reinterpret_cast<const float4*>(g_u + (size_t)b * EE)[t];
    if (t == 0) wden_sh = 0.f;
    const float c_b = g_c[b];
    __syncthreads();

    const float* encb = enc + (size_t)b * LL * EE;
    float4 macc = {0.f, 0.f, 0.f, 0.f};

    for (int c0 = lstart; c0 < lend; c0 += 8) {
        const int nr = (lend - c0) < 8 ? (lend - c0) : 8;
        const int lw   = warp >> 1;    // row within chunk
        const int half = warp & 1;     // which half of the 2048-dim dot

        if (lw < nr) {
            const float4* row4 =
                reinterpret_cast<const float4*>(encb + (size_t)(c0 + lw) * EE) + half * 256;
            const float4* us4 = reinterpret_cast<const float4*>(u_s) + half * 256;
            float d = 0.f;
#pragma unroll
            for (int i = 0; i < 8; i++) {
                const int f = lane + 32 * i;
                float4 v  = row4[f];
                float4 uu = us4[f];
                d += v.x * uu.x + v.y * uu.y + v.z * uu.z + v.w * uu.w;
            }
#pragma unroll
            for (int o = 16; o > 0; o >>= 1)
                d += __shfl_xor_sync(0xffffffffu, d, o);
            if (lane == 0) pdot[lw][half] = d;
        }
        __syncthreads();

        if (t < nr)
            wexp_s[t] = __expf(tanhf(pdot[t][0] + pdot[t][1] + c_b));
        __syncthreads();

        if (t == 0) {
            float acc = 0.f;
            for (int r = 0; r < nr; r++) acc += wexp_s[r];
            wden_sh += acc;
        }
        const float4* base = reinterpret_cast<const float4*>(encb + (size_t)c0 * EE) + t;
        for (int r = 0; r < nr; r++) {
            const float wv = wexp_s[r];
            float4 v = base[(size_t)r * (EE / 4)];
            macc.x += wv * v.x; macc.y += wv * v.y;
            macc.z += wv * v.z; macc.w += wv * v.w;
        }
        __syncthreads();
    }

    float* pp = g_fpart + ((size_t)sp * BB + b) * EE;
    reinterpret_cast<float4*>(pp)[t] = macc;
    if (t == 0) g_fden[sp * BB + b] = wden_sh;
}

// =====================================================================
// Launcher
// =====================================================================
extern "C" void kernel_launch(void* const* d_in, const int* in_sizes, int n_in,
                              void* d_out, int out_size) {
    const float* enc = (const float*)d_in[0];  // [128,196,2048]
    const float* dh  = (const float*)d_in[1];  // [128,1024]
    const float* Wq  = (const float*)d_in[2];  // [1024,2048]  (A,E)
    const float* bq  = (const float*)d_in[3];  // [1024]
    const float* Wv  = (const float*)d_in[4];  // [1024,2048]  (A,E)
    const float* bv  = (const float*)d_in[5];  // [1024]
    const float* Wd  = (const float*)d_in[6];  // [1024,1024]  (A,D)
    const float* bd  = (const float*)d_in[7];  // [1024]
    float* out = (float*)d_out;                // [128,1024]

    const size_t smemsz = sizeof(SmemGemm);    // ~106KB, dynamic
    cudaFuncSetAttribute(gemm_tc<false, 0>, cudaFuncAttributeMaxDynamicSharedMemorySize, (int)smemsz);
    cudaFuncSetAttribute(gemm_tc<true, 1>,  cudaFuncAttributeMaxDynamicSharedMemorySize, (int)smemsz);
    cudaFuncSetAttribute(gemm_tc<false, 2>, cudaFuncAttributeMaxDynamicSharedMemorySize, (int)smemsz);

    // 1) dec_q = h @ Wd^T + bd   (NT, K=D=1024, split 8 -> 16x8 = 128 CTAs)
    gemm_tc<false, 0><<<dim3(AA / 64, 8), 256, smemsz>>>(dh, Wd, DD, AA, DD / 8);
    reduce_add_kernel<1, false><<<(BB * AA) / 1024, 256>>>(nullptr, bd, 8, BB * AA, AA);

    // 2) c = dec_q . bq
    cvec_kernel<<<BB, 256>>>(bq);

    // 3) u = dec_q @ Wq          (NN, K=A=1024, split 4 -> 32x4 = 128 CTAs)
    gemm_tc<true, 1><<<dim3(EE / 64, 4), 256, smemsz>>>(nullptr, Wq, AA, EE, AA / 4);
    reduce_add_kernel<2, false><<<(BB * EE) / 1024, 256>>>(nullptr, nullptr, 4, BB * EE, EE);

    // 4) fused: energies + softmax weights + weighted encoder sum (split 2 over L)
    fused_attn_kernel<<<dim3(BB, 2), 512>>>(enc);

    // 5) context = (P0+P1) @ Wv^T, then *1/sum(w) + bv in reduce epilogue
    //    (NT, K=E=2048, split 8 -> 16x8 = 128 CTAs)
    gemm_tc<false, 2><<<dim3(AA / 64, 8), 256, smemsz>>>(nullptr, Wv, EE, AA, EE / 8);
    reduce_add_kernel<0, true><<<(BB * AA) / 1024, 256>>>(out, bv, 8, BB * AA, AA);
}